// round 12
// baseline (speedup 1.0000x reference)
#include <cuda_runtime.h>
#include <cstdint>

#define BATCH   16384
#define NCLS    1024
#define FEAT    512
#define F4      (FEAT / 4)     // 128 float4 per feature row
#define ALPHA   0.5f

#define CPB     8              // classes per block
#define NBLK    (NCLS / CPB)   // 128 blocks -> one balanced wave
#define THREADS 512            // 16 warps, apportioned to 8 classes by count
#define NWARP   16
#define MAXS    64             // rows per class cap (Poisson(16))

// Phase 1: per-block label scan -> per-class row lists (R11-proven).
// Phase 1.5: greedy warp apportionment: each of the 8 spare warps goes to the
//            class with max rows-per-warp => per-warp load ~= total/16,
//            independent of class skew (kills the straggler barrier tax).
// Phase 2: warp (class k, rank r of nw) processes rows r, r+nw, ... with
//          2-row unroll (8 independent LDG.E.128 in flight). ||f-ctr||^2 via
//          shfl -> out[b]; class feature sum in regs (warp works on ONE
//          class, so acc is a valid partial); team merged via smem by rank 0.
__global__ void __launch_bounds__(THREADS, 1)
k_all(const float4* __restrict__ features,
      const float4* __restrict__ centers,
      const int4*   __restrict__ labels4,
      float* __restrict__ out) {
    __shared__ int    s_cnt[CPB];
    __shared__ int    s_list[CPB][MAXS];
    __shared__ int    s_wcls[NWARP], s_wrank[NWARP], s_wnw[NWARP];
    __shared__ float4 s_part[NWARP][F4];     // 32KB per-warp partials

    const int tid = threadIdx.x;
    const int c0  = blockIdx.x * CPB;

    if (tid < CPB) s_cnt[tid] = 0;
    __syncthreads();

    // ---- Phase 1: scan all labels, collect rows of classes c0..c0+7
    #pragma unroll
    for (int it = 0; it < (BATCH / 4) / THREADS; ++it) {   // 8 iterations
        const int idx = it * THREADS + tid;
        const int4 v  = labels4[idx];
        const int  b  = idx * 4;
        int d;
        d = v.x - c0; if ((unsigned)d < CPB) { int s = atomicAdd(&s_cnt[d], 1); if (s < MAXS) s_list[d][s] = b;     }
        d = v.y - c0; if ((unsigned)d < CPB) { int s = atomicAdd(&s_cnt[d], 1); if (s < MAXS) s_list[d][s] = b + 1; }
        d = v.z - c0; if ((unsigned)d < CPB) { int s = atomicAdd(&s_cnt[d], 1); if (s < MAXS) s_list[d][s] = b + 2; }
        d = v.w - c0; if ((unsigned)d < CPB) { int s = atomicAdd(&s_cnt[d], 1); if (s < MAXS) s_list[d][s] = b + 3; }
    }
    __syncthreads();

    // ---- Phase 1.5: greedy apportionment of 16 warps to 8 classes
    if (tid == 0) {
        int nw[CPB];
        int cc[CPB];
        #pragma unroll
        for (int k = 0; k < CPB; k++) {
            nw[k] = 1;
            cc[k] = min(s_cnt[k], MAXS);
        }
        #pragma unroll
        for (int rep = 0; rep < NWARP - CPB; rep++) {   // 8 spare warps
            int bk = 0; float best = -1.f;
            #pragma unroll
            for (int k = 0; k < CPB; k++) {
                const float load = (float)cc[k] / (float)nw[k];
                if (load > best) { best = load; bk = k; }
            }
            nw[bk]++;
        }
        int wpos = 0;
        #pragma unroll
        for (int k = 0; k < CPB; k++)
            for (int r = 0; r < nw[k]; r++) {
                s_wcls[wpos] = k; s_wrank[wpos] = r; s_wnw[wpos] = nw[k];
                wpos++;
            }
    }
    __syncthreads();

    // ---- Phase 2
    const int w  = tid >> 5;
    const int l  = tid & 31;
    const int k  = s_wcls[w];
    const int r  = s_wrank[w];
    const int nw = s_wnw[w];
    const int c  = c0 + k;
    const int cnt = min(s_cnt[k], MAXS);

    float4 ctr[4];
    #pragma unroll
    for (int j = 0; j < 4; j++)
        ctr[j] = centers[c * F4 + l + 32 * j];

    float4 acc[4];
    #pragma unroll
    for (int j = 0; j < 4; j++)
        acc[j] = make_float4(0.f, 0.f, 0.f, 0.f);

    int i = r;
    for (; i + nw < cnt; i += 2 * nw) {
        const int b0 = s_list[k][i];
        const int b1 = s_list[k][i + nw];
        float4 f0[4], f1[4];
        #pragma unroll
        for (int j = 0; j < 4; j++) {
            f0[j] = features[b0 * F4 + l + 32 * j];
            f1[j] = features[b1 * F4 + l + 32 * j];
        }
        float sq0 = 0.f, sq1 = 0.f;
        #pragma unroll
        for (int j = 0; j < 4; j++) {
            acc[j].x += f0[j].x + f1[j].x;
            acc[j].y += f0[j].y + f1[j].y;
            acc[j].z += f0[j].z + f1[j].z;
            acc[j].w += f0[j].w + f1[j].w;
            float dx, dy, dz, dw;
            dx = f0[j].x - ctr[j].x; dy = f0[j].y - ctr[j].y;
            dz = f0[j].z - ctr[j].z; dw = f0[j].w - ctr[j].w;
            sq0 += dx * dx + dy * dy + dz * dz + dw * dw;
            dx = f1[j].x - ctr[j].x; dy = f1[j].y - ctr[j].y;
            dz = f1[j].z - ctr[j].z; dw = f1[j].w - ctr[j].w;
            sq1 += dx * dx + dy * dy + dz * dz + dw * dw;
        }
        #pragma unroll
        for (int o = 16; o; o >>= 1) {
            sq0 += __shfl_xor_sync(0xffffffffu, sq0, o);
            sq1 += __shfl_xor_sync(0xffffffffu, sq1, o);
        }
        if (l == 0) { out[b0] = sq0; out[b1] = sq1; }
    }
    if (i < cnt) {
        const int b = s_list[k][i];
        float sq = 0.f;
        #pragma unroll
        for (int j = 0; j < 4; j++) {
            const float4 f = features[b * F4 + l + 32 * j];
            acc[j].x += f.x; acc[j].y += f.y; acc[j].z += f.z; acc[j].w += f.w;
            const float dx = f.x - ctr[j].x;
            const float dy = f.y - ctr[j].y;
            const float dz = f.z - ctr[j].z;
            const float dw = f.w - ctr[j].w;
            sq += dx * dx + dy * dy + dz * dz + dw * dw;
        }
        #pragma unroll
        for (int o = 16; o; o >>= 1)
            sq += __shfl_xor_sync(0xffffffffu, sq, o);
        if (l == 0) out[b] = sq;
    }

    // ---- team merge: non-rank0 warps publish; rank0 sums its contiguous team
    if (r != 0) {
        #pragma unroll
        for (int j = 0; j < 4; j++)
            s_part[w][l + 32 * j] = acc[j];
    }
    __syncthreads();

    if (r == 0) {
        #pragma unroll
        for (int j = 0; j < 4; j++) {
            for (int t = 1; t < nw; t++) {
                const float4 p = s_part[w + t][l + 32 * j];
                acc[j].x += p.x; acc[j].y += p.y;
                acc[j].z += p.z; acc[j].w += p.w;
            }
        }
        const float fc = (float)cnt;
        const float sc = ALPHA / (fc + 1.0f);
        float4* __restrict__ cout = reinterpret_cast<float4*>(out + BATCH);
        #pragma unroll
        for (int j = 0; j < 4; j++) {
            const float4 m = ctr[j];
            float4 nc;
            // delta = cnt*ctr - sum_features ; new = ctr - alpha*delta/(cnt+1)
            nc.x = m.x - sc * (fc * m.x - acc[j].x);
            nc.y = m.y - sc * (fc * m.y - acc[j].y);
            nc.z = m.z - sc * (fc * m.z - acc[j].z);
            nc.w = m.w - sc * (fc * m.w - acc[j].w);
            cout[c * F4 + l + 32 * j] = nc;
        }
    }
}

extern "C" void kernel_launch(void* const* d_in, const int* in_sizes, int n_in,
                              void* d_out, int out_size) {
    const float4* features = (const float4*)d_in[0];   // [16384, 512] f32
    const float4* centers  = (const float4*)d_in[1];   // [1024, 512] f32
    const int4*   labels4  = (const int4*)d_in[2];     // [16384] i32
    float*        out      = (float*)d_out;            // [16384 + 1024*512] f32

    k_all<<<NBLK, THREADS>>>(features, centers, labels4, out);
}

// round 13
// speedup vs baseline: 2.3761x; 2.3761x over previous
#include <cuda_runtime.h>
#include <cstdint>

#define BATCH   16384
#define NCLS    1024
#define FEAT    512
#define F4      (FEAT / 4)     // 128 float4 per feature row
#define ALPHA   0.5f

#define CPB     8              // classes per block
#define NBLK    (NCLS / CPB)   // 128 blocks -> one balanced wave
#define THREADS 768            // 24 warps: class k owned by warps {3k,3k+1,3k+2}
#define NWARP   24
#define WPC     3              // warps per class
#define MAXS    64             // rows per class cap (Poisson(16))

// dynamic smem: per-warp partial class sums for the 3-way merge
#define PART_BYTES (NWARP * F4 * 16)   // 24 * 128 * float4 = 48 KB

// Phase 1: per-block label scan -> per-class row lists (R11-proven shape).
// Phase 2: class k owned by 3 warps (rows r, r+3, ...), 2-row unroll =
//          8 independent LDG.E.128 in flight per warp; 24 warps/SM => 24KB
//          outstanding (1.5x R11). ||f-ctr||^2 via shfl -> out[b]; class
//          feature sum in regs; 3-way merge via dynamic smem; center written
//          by rank-0 warp.
__global__ void __launch_bounds__(THREADS, 1)
k_all(const float4* __restrict__ features,
      const float4* __restrict__ centers,
      const int4*   __restrict__ labels4,
      float* __restrict__ out) {
    __shared__ int s_cnt[CPB];
    __shared__ int s_list[CPB][MAXS];
    extern __shared__ float4 s_part[];     // [NWARP][F4]

    const int tid = threadIdx.x;
    const int c0  = blockIdx.x * CPB;

    if (tid < CPB) s_cnt[tid] = 0;
    __syncthreads();

    // ---- Phase 1: scan all labels, collect rows of classes c0..c0+7
    #pragma unroll
    for (int it = 0; it < 6; ++it) {               // ceil(4096/768) = 6
        const int idx = it * THREADS + tid;
        if (idx < BATCH / 4) {
            const int4 v = labels4[idx];
            const int  b = idx * 4;
            int d;
            d = v.x - c0; if ((unsigned)d < CPB) { int s = atomicAdd(&s_cnt[d], 1); if (s < MAXS) s_list[d][s] = b;     }
            d = v.y - c0; if ((unsigned)d < CPB) { int s = atomicAdd(&s_cnt[d], 1); if (s < MAXS) s_list[d][s] = b + 1; }
            d = v.z - c0; if ((unsigned)d < CPB) { int s = atomicAdd(&s_cnt[d], 1); if (s < MAXS) s_list[d][s] = b + 2; }
            d = v.w - c0; if ((unsigned)d < CPB) { int s = atomicAdd(&s_cnt[d], 1); if (s < MAXS) s_list[d][s] = b + 3; }
        }
    }
    __syncthreads();

    // ---- Phase 2: 3 warps per class, 2-row unroll
    const int w = tid >> 5;
    const int l = tid & 31;
    const int k = w / WPC;                 // class 0..7 within block
    const int r = w - k * WPC;             // rank 0..2 within class team
    const int c = c0 + k;
    const int cnt = min(s_cnt[k], MAXS);

    float4 ctr[4];
    #pragma unroll
    for (int j = 0; j < 4; j++)
        ctr[j] = centers[c * F4 + l + 32 * j];

    float4 acc[4];
    #pragma unroll
    for (int j = 0; j < 4; j++)
        acc[j] = make_float4(0.f, 0.f, 0.f, 0.f);

    int i = r;
    for (; i + WPC < cnt; i += 2 * WPC) {
        const int b0 = s_list[k][i];
        const int b1 = s_list[k][i + WPC];
        float4 f0[4], f1[4];
        #pragma unroll
        for (int j = 0; j < 4; j++) {
            f0[j] = features[b0 * F4 + l + 32 * j];
            f1[j] = features[b1 * F4 + l + 32 * j];
        }
        float sq0 = 0.f, sq1 = 0.f;
        #pragma unroll
        for (int j = 0; j < 4; j++) {
            acc[j].x += f0[j].x + f1[j].x;
            acc[j].y += f0[j].y + f1[j].y;
            acc[j].z += f0[j].z + f1[j].z;
            acc[j].w += f0[j].w + f1[j].w;
            float dx, dy, dz, dw;
            dx = f0[j].x - ctr[j].x; dy = f0[j].y - ctr[j].y;
            dz = f0[j].z - ctr[j].z; dw = f0[j].w - ctr[j].w;
            sq0 += dx * dx + dy * dy + dz * dz + dw * dw;
            dx = f1[j].x - ctr[j].x; dy = f1[j].y - ctr[j].y;
            dz = f1[j].z - ctr[j].z; dw = f1[j].w - ctr[j].w;
            sq1 += dx * dx + dy * dy + dz * dz + dw * dw;
        }
        #pragma unroll
        for (int o = 16; o; o >>= 1) {
            sq0 += __shfl_xor_sync(0xffffffffu, sq0, o);
            sq1 += __shfl_xor_sync(0xffffffffu, sq1, o);
        }
        if (l == 0) { out[b0] = sq0; out[b1] = sq1; }
    }
    if (i < cnt) {
        const int b = s_list[k][i];
        float sq = 0.f;
        #pragma unroll
        for (int j = 0; j < 4; j++) {
            const float4 f = features[b * F4 + l + 32 * j];
            acc[j].x += f.x; acc[j].y += f.y; acc[j].z += f.z; acc[j].w += f.w;
            const float dx = f.x - ctr[j].x;
            const float dy = f.y - ctr[j].y;
            const float dz = f.z - ctr[j].z;
            const float dw = f.w - ctr[j].w;
            sq += dx * dx + dy * dy + dz * dz + dw * dw;
        }
        #pragma unroll
        for (int o = 16; o; o >>= 1)
            sq += __shfl_xor_sync(0xffffffffu, sq, o);
        if (l == 0) out[b] = sq;
    }

    // ---- 3-way team merge: ranks 1,2 publish; rank 0 reduces + writes center
    if (r != 0) {
        #pragma unroll
        for (int j = 0; j < 4; j++)
            s_part[w * F4 + l + 32 * j] = acc[j];
    }
    __syncthreads();

    if (r == 0) {
        #pragma unroll
        for (int j = 0; j < 4; j++) {
            const float4 p1 = s_part[(w + 1) * F4 + l + 32 * j];
            const float4 p2 = s_part[(w + 2) * F4 + l + 32 * j];
            acc[j].x += p1.x + p2.x;
            acc[j].y += p1.y + p2.y;
            acc[j].z += p1.z + p2.z;
            acc[j].w += p1.w + p2.w;
        }
        const float fc = (float)cnt;
        const float sc = ALPHA / (fc + 1.0f);
        float4* __restrict__ cout = reinterpret_cast<float4*>(out + BATCH);
        #pragma unroll
        for (int j = 0; j < 4; j++) {
            const float4 m = ctr[j];
            float4 nc;
            // delta = cnt*ctr - sum_features ; new = ctr - alpha*delta/(cnt+1)
            nc.x = m.x - sc * (fc * m.x - acc[j].x);
            nc.y = m.y - sc * (fc * m.y - acc[j].y);
            nc.z = m.z - sc * (fc * m.z - acc[j].z);
            nc.w = m.w - sc * (fc * m.w - acc[j].w);
            cout[c * F4 + l + 32 * j] = nc;
        }
    }
}

extern "C" void kernel_launch(void* const* d_in, const int* in_sizes, int n_in,
                              void* d_out, int out_size) {
    const float4* features = (const float4*)d_in[0];   // [16384, 512] f32
    const float4* centers  = (const float4*)d_in[1];   // [1024, 512] f32
    const int4*   labels4  = (const int4*)d_in[2];     // [16384] i32
    float*        out      = (float*)d_out;            // [16384 + 1024*512] f32

    static bool attr_set = false;
    if (!attr_set) {
        cudaFuncSetAttribute(k_all, cudaFuncAttributeMaxDynamicSharedMemorySize,
                             PART_BYTES);
        attr_set = true;
    }
    k_all<<<NBLK, THREADS, PART_BYTES>>>(features, centers, labels4, out);
}